// round 10
// baseline (speedup 1.0000x reference)
#include <cuda_runtime.h>
#include <math_constants.h>
#include <cstdint>

// Shapes (fixed)
#define Bz 32
#define Cc 256
#define HW 1024
#define Nn 32768
#define Kk 1024
#define Dd 256
#define TOTAL_Z 8388608

#define MARGIN 2e-3f
#define CAP 32
#define MT 128          // rows per CTA

// gemm kernel smem map (bytes)
#define SM_CNT   0          // 128 ints
#define SM_CAND  512        // 128*32*4 = 16384
#define SM_A     17408      // 131072 (full-D A, fragment order)
#define SM_B     148480     // 2 x 32768 (B chunk, fragment order)
#define SM_TOTAL 214016
#define OPAD 132            // output kernel cbT padding

__device__ float  g_B[Kk];          // ||c_k||^2 (sequential fp32 chain)
__device__ float  g_ct[Kk * Dd];    // tf32 codebook in mma-fragment order
__device__ int    g_idx[Nn];
__device__ double g_loss;

__device__ __forceinline__ uint32_t smem_u32(const void* p) {
    uint32_t a;
    asm("{ .reg .u64 t; cvta.to.shared.u64 t, %1; cvt.u32.u64 %0, t; }"
        : "=r"(a) : "l"(p));
    return a;
}
__device__ __forceinline__ unsigned tf32r(float v) {
    unsigned t; asm("cvt.rna.tf32.f32 %0, %1;" : "=r"(t) : "f"(v)); return t;
}
__device__ __forceinline__ void mma_t(float c[4], float4 a, float2 b) {
    asm volatile(
        "mma.sync.aligned.m16n8k8.row.col.f32.tf32.tf32.f32 "
        "{%0,%1,%2,%3},{%4,%5,%6,%7},{%8,%9},{%0,%1,%2,%3};"
        : "+f"(c[0]), "+f"(c[1]), "+f"(c[2]), "+f"(c[3])
        : "r"(__float_as_uint(a.x)), "r"(__float_as_uint(a.y)),
          "r"(__float_as_uint(a.z)), "r"(__float_as_uint(a.w)),
          "r"(__float_as_uint(b.x)), "r"(__float_as_uint(b.y)));
}

// ---- prep: codebook norms + tf32 fragment-order transpose ----
// Fragment layout: for code n, dim d:
//   t=n>>7, wn=(n>>5)&3, j=(n>>3)&3, tq=n&7 ; c4=d>>6, s=(d>>3)&7, kk=d&7
//   r=kk>>2, tr=kk&3, lane=tq*4+tr
//   g_ct[(t*4+c4)*8192 + ((s*16+wn*4+j)*32+lane)*2 + r]
__global__ void prep_cb_kernel(const float* __restrict__ cb) {
    int n = blockIdx.x * blockDim.x + threadIdx.x;
    if (n == 0) g_loss = 0.0;
    if (n < Kk) {
        int t = n >> 7, wn = (n >> 5) & 3, j = (n >> 3) & 3, tq = n & 7;
        float s_ = 0.f;
        #pragma unroll 8
        for (int d = 0; d < Dd; d++) {
            float v = cb[n * Dd + d];
            s_ = __fadd_rn(s_, __fmul_rn(v, v));
            int c4 = d >> 6, ss = (d >> 3) & 7, kk = d & 7;
            int r = kk >> 2, tr = kk & 3, lane = tq * 4 + tr;
            size_t a = (size_t)(t * 4 + c4) * 8192 +
                       ((ss * 16 + wn * 4 + j) * 32 + lane) * 2 + r;
            ((unsigned*)g_ct)[a] = tf32r(v);
        }
        g_B[n] = s_;
    }
}

// ---- B chunk staging: contiguous cp.async (32 KB per chunk) ----
__device__ __forceinline__ void issueB(char* smem, int tid, int p, int buf) {
    const float* src = g_ct + (size_t)p * 8192 + tid * 4;
    uint32_t dst = smem_u32(smem + SM_B + buf * 32768) + tid * 16;
    #pragma unroll
    for (int it = 0; it < 8; it++)
        asm volatile("cp.async.cg.shared.global [%0], [%1], 16;"
                     :: "r"(dst + it * 4096), "l"(src + it * 1024));
    asm volatile("cp.async.commit_group;");
}

// ============== fused mma.sync GEMM + streaming argmin ==================
// 256 thr = 8 warps (2m x 4n), warp tile 64m x 32n, mma m16n8k8 tf32.
// A full-D resident in fragment order; B streamed per (ntile, 64-d chunk).
__global__ void __launch_bounds__(256, 1)
gemm_argmin_kernel(const float* __restrict__ z, const float* __restrict__ cb) {
    extern __shared__ char smem[];
    int*   cnt  = (int*)smem;
    int*   cand = (int*)(smem + SM_CAND);
    float* As   = (float*)(smem + SM_A);
    float* Bs   = (float*)(smem + SM_B);

    int tid = threadIdx.x, wid = tid >> 5, lane = tid & 31;
    int wm = wid & 1, wn = wid >> 1, tq = lane >> 2, tr = lane & 3;
    int n0 = blockIdx.x * MT, b = n0 >> 10, hw0 = n0 & 1023;

    if (tid < MT) cnt[tid] = 0;

    // Stage A: z tile (tf32), pre-permuted to fragment order.
    #pragma unroll 4
    for (int it = 0; it < 32; it++) {
        int d = wid + it * 8;
        float4 v = *(const float4*)(z + (size_t)b * Cc * HW +
                                    (size_t)d * HW + hw0 + lane * 4);
        int sg = d >> 3, kk = d & 7, kqh = kk >> 2, ktr = kk & 3;
        float vv[4] = {v.x, v.y, v.z, v.w};
        #pragma unroll
        for (int q4 = 0; q4 < 4; q4++) {
            int r = lane * 4 + q4;
            int awm = r >> 6, ai = (r >> 4) & 3, ah = (r >> 3) & 1, atq = r & 7;
            ((unsigned*)As)[((sg * 8 + awm * 4 + ai) * 32 + atq * 4 + ktr) * 4 +
                            kqh * 2 + ah] = tf32r(vv[q4]);
        }
    }

    issueB(smem, tid, 0, 0);
    __syncthreads();

    float accf[4][4][4];
    float runm[4][2];
    #pragma unroll
    for (int i = 0; i < 4; i++)
        #pragma unroll
        for (int h = 0; h < 2; h++) runm[i][h] = CUDART_INF_F;

    #pragma unroll 1
    for (int p = 0; p < 32; p++) {
        int buf = p & 1, c4 = p & 3, t = p >> 2;
        if (p < 31) {
            issueB(smem, tid, p + 1, buf ^ 1);
            asm volatile("cp.async.wait_group 1;" ::: "memory");
        } else {
            asm volatile("cp.async.wait_group 0;" ::: "memory");
        }
        __syncthreads();

        if (c4 == 0) {
            #pragma unroll
            for (int i = 0; i < 4; i++)
                #pragma unroll
                for (int j = 0; j < 4; j++)
                    #pragma unroll
                    for (int q = 0; q < 4; q++) accf[i][j][q] = 0.f;
        }

        const float* Bb = Bs + buf * 8192;
        #pragma unroll
        for (int s = 0; s < 8; s++) {
            int sg = c4 * 8 + s;
            float4 a[4];
            #pragma unroll
            for (int i = 0; i < 4; i++)
                a[i] = *(const float4*)(As + ((sg * 8 + wm * 4 + i) * 32 + lane) * 4);
            float2 bb[4];
            #pragma unroll
            for (int j = 0; j < 4; j++)
                bb[j] = *(const float2*)(Bb + ((s * 16 + wn * 4 + j) * 32 + lane) * 2);
            #pragma unroll
            for (int i = 0; i < 4; i++)
                #pragma unroll
                for (int j = 0; j < 4; j++)
                    mma_t(accf[i][j], a[i], bb[j]);
        }

        if (c4 == 3) {
            // epilogue: d' = fmaf(-2, dot, B_k)  (Z dropped: row-constant shift)
            #pragma unroll
            for (int j = 0; j < 4; j++) {
                int k0 = t * 128 + wn * 32 + j * 8 + 2 * tr;
                float2 Bv = *(const float2*)&g_B[k0];
                #pragma unroll
                for (int i = 0; i < 4; i++)
                    #pragma unroll
                    for (int h = 0; h < 2; h++) {
                        float d0 = fmaf(-2.f, accf[i][j][h * 2 + 0], Bv.x);
                        float d1 = fmaf(-2.f, accf[i][j][h * 2 + 1], Bv.y);
                        accf[i][j][h * 2 + 0] = d0;
                        accf[i][j][h * 2 + 1] = d1;
                        runm[i][h] = fminf(runm[i][h], fminf(d0, d1));
                    }
            }
            #pragma unroll
            for (int i = 0; i < 4; i++)
                #pragma unroll
                for (int h = 0; h < 2; h++) {
                    float th = runm[i][h] + MARGIN;
                    int row = wm * 64 + i * 16 + h * 8 + tq;
                    #pragma unroll
                    for (int j = 0; j < 4; j++) {
                        int k0 = t * 128 + wn * 32 + j * 8 + 2 * tr;
                        if (accf[i][j][h * 2 + 0] <= th) {
                            int pos = atomicAdd(&cnt[row], 1);
                            if (pos < CAP) cand[row * CAP + pos] = k0;
                        }
                        if (accf[i][j][h * 2 + 1] <= th) {
                            int pos = atomicAdd(&cnt[row], 1);
                            if (pos < CAP) cand[row * CAP + pos] = k0 + 1;
                        }
                    }
                }
        }
        __syncthreads();
    }

    // -------- exact fp32 rescore (reuse A/B smem for exact z rows) --------
    float* zrow = (float*)(smem + SM_A);     // [128][257]
    #pragma unroll 4
    for (int it = 0; it < 32; it++) {
        int d = wid + it * 8;
        float4 v = *(const float4*)(z + (size_t)b * Cc * HW +
                                    (size_t)d * HW + hw0 + lane * 4);
        int r = lane * 4;
        zrow[(r    ) * 257 + d] = v.x;
        zrow[(r + 1) * 257 + d] = v.y;
        zrow[(r + 2) * 257 + d] = v.z;
        zrow[(r + 3) * 257 + d] = v.w;
    }
    __syncthreads();

    int rr = tid >> 1, part = tid & 1;
    int cr = cnt[rr];
    const float* zp = zrow + rr * 257;
    // Zn: sequential chain identical to reference / prior passing rounds
    float Zn = 0.f;
    #pragma unroll 8
    for (int d = 0; d < Dd; d++) Zn = __fadd_rn(Zn, __fmul_rn(zp[d], zp[d]));

    float bv = CUDART_INF_F; int bk = 0x7fffffff;
    if (cr <= CAP) {
        for (int ci = part; ci < cr; ci += 2) {
            int k = cand[rr * CAP + ci];
            const float* crow = cb + (size_t)k * Dd;
            float acc = 0.f;
            #pragma unroll 8
            for (int d = 0; d < Dd; d++) acc = fmaf(zp[d], crow[d], acc);
            float dv = fmaf(-2.0f, acc, __fadd_rn(Zn, g_B[k]));
            if (dv < bv || (dv == bv && k < bk)) { bv = dv; bk = k; }
        }
    } else {  // overflow fallback: exact scan of all codes (correct, ~never)
        for (int k = part; k < Kk; k += 2) {
            const float* crow = cb + (size_t)k * Dd;
            float acc = 0.f;
            #pragma unroll 8
            for (int d = 0; d < Dd; d++) acc = fmaf(zp[d], crow[d], acc);
            float dv = fmaf(-2.0f, acc, __fadd_rn(Zn, g_B[k]));
            if (dv < bv || (dv == bv && k < bk)) { bv = dv; bk = k; }
        }
    }
    float ov = __shfl_xor_sync(~0u, bv, 1);
    int   ok = __shfl_xor_sync(~0u, bk, 1);
    if (ov < bv || (ov == bv && ok < bk)) { bv = ov; bk = ok; }
    if (part == 0) g_idx[n0 + rr] = bk;
}

// ---- output: 128-row CTA, transposed smem codebook tile, all-float4 ----
__global__ void __launch_bounds__(512)
output_kernel(const float* __restrict__ z, const float* __restrict__ cb,
              float* __restrict__ out) {
    extern __shared__ float cbT[];           // [256][OPAD]
    __shared__ double wsum[16];

    int tid = threadIdx.x;
    int n0 = blockIdx.x * 128, b = n0 >> 10, hw0 = n0 & 1023;

    // gather 128 codebook rows -> transposed tile (coalesced float4 reads)
    {
        int r = tid & 127, cg = tid >> 7;    // 4 thread-groups over channels
        int idx = g_idx[n0 + r];
        const float4* src = (const float4*)(cb + (size_t)idx * Dd) + cg * 16;
        #pragma unroll
        for (int m = 0; m < 16; m++) {
            float4 v = src[m];
            int c = cg * 64 + m * 4;
            cbT[(c    ) * OPAD + r] = v.x;
            cbT[(c + 1) * OPAD + r] = v.y;
            cbT[(c + 2) * OPAD + r] = v.z;
            cbT[(c + 3) * OPAD + r] = v.w;
        }
    }
    __syncthreads();

    int lane = tid & 31, w = tid >> 5;       // 16 warps over channels
    const float* zb = z   + (size_t)b * Cc * HW + hw0 + lane * 4;
    float*       ob = out + (size_t)b * Cc * HW + hw0 + lane * 4;

    double accd = 0.0;
    #pragma unroll 4
    for (int c = w; c < Cc; c += 16) {
        float4 zv = *(const float4*)(zb + (size_t)c * HW);
        float4 cq = *(const float4*)(cbT + c * OPAD + lane * 4);
        float4 o;
        float dx = __fsub_rn(cq.x, zv.x); o.x = __fadd_rn(zv.x, dx);
        float dy = __fsub_rn(cq.y, zv.y); o.y = __fadd_rn(zv.y, dy);
        float dz = __fsub_rn(cq.z, zv.z); o.z = __fadd_rn(zv.z, dz);
        float dw = __fsub_rn(cq.w, zv.w); o.w = __fadd_rn(zv.w, dw);
        *(float4*)(ob + (size_t)c * HW) = o;
        accd += (double)dx * dx + (double)dy * dy +
                (double)dz * dz + (double)dw * dw;
    }
    #pragma unroll
    for (int o = 16; o; o >>= 1) accd += __shfl_down_sync(0xffffffffu, accd, o);
    if (lane == 0) wsum[w] = accd;
    __syncthreads();
    if (tid == 0) {
        double t = 0.0;
        #pragma unroll
        for (int k = 0; k < 16; k++) t += wsum[k];
        atomicAdd(&g_loss, t);
    }
}

// ---- tail: vq_loss scalar + indices as float ----
__global__ void tail_kernel(float* __restrict__ out, int out_size) {
    int n = blockIdx.x * blockDim.x + threadIdx.x;
    if (n < Nn && out_size >= TOTAL_Z + 1 + Nn)
        out[TOTAL_Z + 1 + n] = (float)g_idx[n];
    if (n == 0 && out_size > TOTAL_Z) {
        double mean = g_loss * (1.0 / (double)TOTAL_Z);
        float cl = (float)mean;
        out[TOTAL_Z] = __fadd_rn(cl, __fmul_rn(0.25f, cl));
    }
}

extern "C" void kernel_launch(void* const* d_in, const int* in_sizes, int n_in,
                              void* d_out, int out_size) {
    const float* z  = (const float*)d_in[0];
    const float* cb = (const float*)d_in[1];
    float* out = (float*)d_out;

    cudaFuncSetAttribute(gemm_argmin_kernel,
                         cudaFuncAttributeMaxDynamicSharedMemorySize, SM_TOTAL);
    const int osmem = 256 * OPAD * (int)sizeof(float);   // 135168
    cudaFuncSetAttribute(output_kernel,
                         cudaFuncAttributeMaxDynamicSharedMemorySize, osmem);

    prep_cb_kernel<<<4, 256>>>(cb);
    gemm_argmin_kernel<<<Nn / MT, 256, SM_TOTAL>>>(z, cb);
    output_kernel<<<Nn / 128, 512, osmem>>>(z, cb, out);
    tail_kernel<<<128, 256>>>(out, out_size);
}

// round 11
// speedup vs baseline: 21.5234x; 21.5234x over previous
#include <cuda_runtime.h>
#include <math_constants.h>
#include <cstdint>

// Shapes (fixed)
#define Bz 32
#define Cc 256
#define HW 1024
#define Nn 32768
#define Kk 1024
#define Dd 256
#define TOTAL_Z 8388608

#define MARGIN 2e-3f
#define CAP 48
#define MT 128          // rows per CTA

// gemm kernel smem map (bytes)
#define SM_CNT   0          // 128 ints
#define SM_ROWM  512        // 128 uints (encoded row min)
#define SM_CAND  1024       // 128*48*4 = 24576
#define SM_A     25600      // 131072 (full-D A, fragment order)
#define SM_B     156672     // 2 x 32768 (B chunk, fragment order)
#define SM_TOTAL 222208
#define SM_ZROW  SM_A       // reuse A+B region after GEMM: 128*260*4
#define ZRPAD 260
#define OPAD 132            // output kernel cbT padding

__device__ float  g_B[Kk];          // ||c_k||^2 (sequential fp32 chain)
__device__ float  g_ct[Kk * Dd];    // tf32 codebook in mma-fragment order
__device__ int    g_idx[Nn];
__device__ double g_loss;

__device__ __forceinline__ uint32_t smem_u32(const void* p) {
    uint32_t a;
    asm("{ .reg .u64 t; cvta.to.shared.u64 t, %1; cvt.u32.u64 %0, t; }"
        : "=r"(a) : "l"(p));
    return a;
}
__device__ __forceinline__ unsigned tf32r(float v) {
    unsigned t; asm("cvt.rna.tf32.f32 %0, %1;" : "=r"(t) : "f"(v)); return t;
}
// order-preserving float<->uint map (for unsigned atomicMin)
__device__ __forceinline__ unsigned fenc(float f) {
    unsigned u = __float_as_uint(f);
    return (u & 0x80000000u) ? ~u : (u | 0x80000000u);
}
__device__ __forceinline__ float fdec(unsigned k) {
    unsigned u = (k & 0x80000000u) ? (k & 0x7fffffffu) : ~k;
    return __uint_as_float(u);
}
__device__ __forceinline__ void mma_t(float c[4], float4 a, float2 b) {
    asm volatile(
        "mma.sync.aligned.m16n8k8.row.col.f32.tf32.tf32.f32 "
        "{%0,%1,%2,%3},{%4,%5,%6,%7},{%8,%9},{%0,%1,%2,%3};"
        : "+f"(c[0]), "+f"(c[1]), "+f"(c[2]), "+f"(c[3])
        : "r"(__float_as_uint(a.x)), "r"(__float_as_uint(a.y)),
          "r"(__float_as_uint(a.z)), "r"(__float_as_uint(a.w)),
          "r"(__float_as_uint(b.x)), "r"(__float_as_uint(b.y)));
}

// ---- prep: codebook norms + tf32 fragment-order transpose ----
__global__ void prep_cb_kernel(const float* __restrict__ cb) {
    int n = blockIdx.x * blockDim.x + threadIdx.x;
    if (n == 0) g_loss = 0.0;
    if (n < Kk) {
        int t = n >> 7, wn = (n >> 5) & 3, j = (n >> 3) & 3, tq = n & 7;
        float s_ = 0.f;
        #pragma unroll 8
        for (int d = 0; d < Dd; d++) {
            float v = cb[n * Dd + d];
            s_ = __fadd_rn(s_, __fmul_rn(v, v));
            int c4 = d >> 6, ss = (d >> 3) & 7, kk = d & 7;
            int r = kk >> 2, tr = kk & 3, lane = tq * 4 + tr;
            size_t a = (size_t)(t * 4 + c4) * 8192 +
                       ((ss * 16 + wn * 4 + j) * 32 + lane) * 2 + r;
            ((unsigned*)g_ct)[a] = tf32r(v);
        }
        g_B[n] = s_;
    }
}

// ---- B chunk staging: contiguous cp.async (32 KB per chunk) ----
__device__ __forceinline__ void issueB(char* smem, int tid, int p, int buf) {
    const float* src = g_ct + (size_t)p * 8192 + tid * 4;
    uint32_t dst = smem_u32(smem + SM_B + buf * 32768) + tid * 16;
    #pragma unroll
    for (int it = 0; it < 8; it++)
        asm volatile("cp.async.cg.shared.global [%0], [%1], 16;"
                     :: "r"(dst + it * 4096), "l"(src + it * 1024));
    asm volatile("cp.async.commit_group;");
}

// ============== fused mma.sync GEMM + row-global streaming argmin ========
__global__ void __launch_bounds__(256, 1)
gemm_argmin_kernel(const float* __restrict__ z, const float* __restrict__ cb) {
    extern __shared__ char smem[];
    int*      cnt  = (int*)smem;
    unsigned* rowm = (unsigned*)(smem + SM_ROWM);
    int*      cand = (int*)(smem + SM_CAND);
    float*    As   = (float*)(smem + SM_A);
    float*    Bs   = (float*)(smem + SM_B);

    int tid = threadIdx.x, wid = tid >> 5, lane = tid & 31;
    int wm = wid & 1, wn = wid >> 1, tq = lane >> 2, tr = lane & 3;
    int n0 = blockIdx.x * MT, b = n0 >> 10, hw0 = n0 & 1023;

    if (tid < MT) { cnt[tid] = 0; rowm[tid] = 0xFF800000u; }  // enc(+inf)

    // Stage A: z tile (tf32), pre-permuted to fragment order.
    #pragma unroll 4
    for (int it = 0; it < 32; it++) {
        int d = wid + it * 8;
        float4 v = *(const float4*)(z + (size_t)b * Cc * HW +
                                    (size_t)d * HW + hw0 + lane * 4);
        int sg = d >> 3, kk = d & 7, kqh = kk >> 2, ktr = kk & 3;
        float vv[4] = {v.x, v.y, v.z, v.w};
        #pragma unroll
        for (int q4 = 0; q4 < 4; q4++) {
            int r = lane * 4 + q4;
            int awm = r >> 6, ai = (r >> 4) & 3, ah = (r >> 3) & 1, atq = r & 7;
            ((unsigned*)As)[((sg * 8 + awm * 4 + ai) * 32 + atq * 4 + ktr) * 4 +
                            kqh * 2 + ah] = tf32r(vv[q4]);
        }
    }

    issueB(smem, tid, 0, 0);
    __syncthreads();

    float accf[4][4][4];

    #pragma unroll 1
    for (int p = 0; p < 32; p++) {
        int buf = p & 1, c4 = p & 3, t = p >> 2;
        if (p < 31) {
            issueB(smem, tid, p + 1, buf ^ 1);
            asm volatile("cp.async.wait_group 1;" ::: "memory");
        } else {
            asm volatile("cp.async.wait_group 0;" ::: "memory");
        }
        __syncthreads();

        if (c4 == 0) {
            #pragma unroll
            for (int i = 0; i < 4; i++)
                #pragma unroll
                for (int j = 0; j < 4; j++)
                    #pragma unroll
                    for (int q = 0; q < 4; q++) accf[i][j][q] = 0.f;
        }

        const float* Bb = Bs + buf * 8192;
        #pragma unroll
        for (int s = 0; s < 8; s++) {
            int sg = c4 * 8 + s;
            float4 a[4];
            #pragma unroll
            for (int i = 0; i < 4; i++)
                a[i] = *(const float4*)(As + ((sg * 8 + wm * 4 + i) * 32 + lane) * 4);
            float2 bb[4];
            #pragma unroll
            for (int j = 0; j < 4; j++)
                bb[j] = *(const float2*)(Bb + ((s * 16 + wn * 4 + j) * 32 + lane) * 2);
            #pragma unroll
            for (int i = 0; i < 4; i++)
                #pragma unroll
                for (int j = 0; j < 4; j++)
                    mma_t(accf[i][j], a[i], bb[j]);
        }

        if (c4 == 3) {
            // phase 1: d' = fmaf(-2, dot, B_k) (Z dropped: row-const shift),
            // fold per-row local min, publish via atomicMin on encoded key.
            float lm[4][2];
            #pragma unroll
            for (int i = 0; i < 4; i++)
                #pragma unroll
                for (int h = 0; h < 2; h++) lm[i][h] = CUDART_INF_F;
            #pragma unroll
            for (int j = 0; j < 4; j++) {
                int k0 = t * 128 + wn * 32 + j * 8 + 2 * tr;
                float2 Bv = *(const float2*)&g_B[k0];
                #pragma unroll
                for (int i = 0; i < 4; i++)
                    #pragma unroll
                    for (int h = 0; h < 2; h++) {
                        float d0 = fmaf(-2.f, accf[i][j][h * 2 + 0], Bv.x);
                        float d1 = fmaf(-2.f, accf[i][j][h * 2 + 1], Bv.y);
                        accf[i][j][h * 2 + 0] = d0;
                        accf[i][j][h * 2 + 1] = d1;
                        lm[i][h] = fminf(lm[i][h], fminf(d0, d1));
                    }
            }
            #pragma unroll
            for (int i = 0; i < 4; i++)
                #pragma unroll
                for (int h = 0; h < 2; h++)
                    atomicMin(&rowm[wm * 64 + i * 16 + h * 8 + tq], fenc(lm[i][h]));
            __syncthreads();
            // phase 2: test against settled row-global running min
            #pragma unroll
            for (int i = 0; i < 4; i++)
                #pragma unroll
                for (int h = 0; h < 2; h++) {
                    int row = wm * 64 + i * 16 + h * 8 + tq;
                    float th = fdec(rowm[row]) + MARGIN;
                    #pragma unroll
                    for (int j = 0; j < 4; j++) {
                        int k0 = t * 128 + wn * 32 + j * 8 + 2 * tr;
                        if (accf[i][j][h * 2 + 0] <= th) {
                            int pos = atomicAdd(&cnt[row], 1);
                            if (pos < CAP) cand[row * CAP + pos] = k0;
                        }
                        if (accf[i][j][h * 2 + 1] <= th) {
                            int pos = atomicAdd(&cnt[row], 1);
                            if (pos < CAP) cand[row * CAP + pos] = k0 + 1;
                        }
                    }
                }
        }
        __syncthreads();
    }

    // -------- exact fp32 rescore (reuse A/B smem for exact z rows) --------
    float* zrow = (float*)(smem + SM_ZROW);     // [128][260], rows 16B-aligned
    #pragma unroll 4
    for (int it = 0; it < 32; it++) {
        int d = wid + it * 8;
        float4 v = *(const float4*)(z + (size_t)b * Cc * HW +
                                    (size_t)d * HW + hw0 + lane * 4);
        int r = lane * 4;
        zrow[(r    ) * ZRPAD + d] = v.x;
        zrow[(r + 1) * ZRPAD + d] = v.y;
        zrow[(r + 2) * ZRPAD + d] = v.z;
        zrow[(r + 3) * ZRPAD + d] = v.w;
    }
    __syncthreads();

    int rr = tid >> 1, part = tid & 1;
    int cr = cnt[rr];
    const float4* zp4 = (const float4*)(zrow + rr * ZRPAD);
    // Zn: sequential chain identical to reference (ascending d)
    float Zn = 0.f;
    #pragma unroll 8
    for (int d4 = 0; d4 < 64; d4++) {
        float4 v = zp4[d4];
        Zn = __fadd_rn(Zn, __fmul_rn(v.x, v.x));
        Zn = __fadd_rn(Zn, __fmul_rn(v.y, v.y));
        Zn = __fadd_rn(Zn, __fmul_rn(v.z, v.z));
        Zn = __fadd_rn(Zn, __fmul_rn(v.w, v.w));
    }

    float bv = CUDART_INF_F; int bk = 0x7fffffff;
    int lim = cr <= CAP ? cr : Kk;      // overflow: exact scan of all codes
    bool ovf = cr > CAP;
    for (int ci = part; ci < lim; ci += 2) {
        int k = ovf ? ci : cand[rr * CAP + ci];
        const float4* c4p = (const float4*)(cb + (size_t)k * Dd);
        float acc = 0.f;
        #pragma unroll 8
        for (int d4 = 0; d4 < 64; d4++) {
            float4 a = zp4[d4];
            float4 c = c4p[d4];
            acc = fmaf(a.x, c.x, acc);
            acc = fmaf(a.y, c.y, acc);
            acc = fmaf(a.z, c.z, acc);
            acc = fmaf(a.w, c.w, acc);
        }
        float dv = fmaf(-2.0f, acc, __fadd_rn(Zn, g_B[k]));
        if (dv < bv || (dv == bv && k < bk)) { bv = dv; bk = k; }
    }
    float ov = __shfl_xor_sync(~0u, bv, 1);
    int   ok = __shfl_xor_sync(~0u, bk, 1);
    if (ov < bv || (ov == bv && ok < bk)) { bv = ov; bk = ok; }
    if (part == 0) g_idx[n0 + rr] = bk;
}

// ---- output: 128-row CTA, transposed smem codebook tile, all-float4 ----
__global__ void __launch_bounds__(512)
output_kernel(const float* __restrict__ z, const float* __restrict__ cb,
              float* __restrict__ out) {
    extern __shared__ float cbT[];           // [256][OPAD]
    __shared__ double wsum[16];

    int tid = threadIdx.x;
    int n0 = blockIdx.x * 128, b = n0 >> 10, hw0 = n0 & 1023;

    {
        int r = tid & 127, cg = tid >> 7;
        int idx = g_idx[n0 + r];
        const float4* src = (const float4*)(cb + (size_t)idx * Dd) + cg * 16;
        #pragma unroll
        for (int m = 0; m < 16; m++) {
            float4 v = src[m];
            int c = cg * 64 + m * 4;
            cbT[(c    ) * OPAD + r] = v.x;
            cbT[(c + 1) * OPAD + r] = v.y;
            cbT[(c + 2) * OPAD + r] = v.z;
            cbT[(c + 3) * OPAD + r] = v.w;
        }
    }
    __syncthreads();

    int lane = tid & 31, w = tid >> 5;
    const float* zb = z   + (size_t)b * Cc * HW + hw0 + lane * 4;
    float*       ob = out + (size_t)b * Cc * HW + hw0 + lane * 4;

    double accd = 0.0;
    #pragma unroll 4
    for (int c = w; c < Cc; c += 16) {
        float4 zv = *(const float4*)(zb + (size_t)c * HW);
        float4 cq = *(const float4*)(cbT + c * OPAD + lane * 4);
        float4 o;
        float dx = __fsub_rn(cq.x, zv.x); o.x = __fadd_rn(zv.x, dx);
        float dy = __fsub_rn(cq.y, zv.y); o.y = __fadd_rn(zv.y, dy);
        float dz = __fsub_rn(cq.z, zv.z); o.z = __fadd_rn(zv.z, dz);
        float dw = __fsub_rn(cq.w, zv.w); o.w = __fadd_rn(zv.w, dw);
        *(float4*)(ob + (size_t)c * HW) = o;
        accd += (double)dx * dx + (double)dy * dy +
                (double)dz * dz + (double)dw * dw;
    }
    #pragma unroll
    for (int o = 16; o; o >>= 1) accd += __shfl_down_sync(0xffffffffu, accd, o);
    if (lane == 0) wsum[w] = accd;
    __syncthreads();
    if (tid == 0) {
        double t = 0.0;
        #pragma unroll
        for (int k = 0; k < 16; k++) t += wsum[k];
        atomicAdd(&g_loss, t);
    }
}

// ---- tail: vq_loss scalar + indices as float ----
__global__ void tail_kernel(float* __restrict__ out, int out_size) {
    int n = blockIdx.x * blockDim.x + threadIdx.x;
    if (n < Nn && out_size >= TOTAL_Z + 1 + Nn)
        out[TOTAL_Z + 1 + n] = (float)g_idx[n];
    if (n == 0 && out_size > TOTAL_Z) {
        double mean = g_loss * (1.0 / (double)TOTAL_Z);
        float cl = (float)mean;
        out[TOTAL_Z] = __fadd_rn(cl, __fmul_rn(0.25f, cl));
    }
}

extern "C" void kernel_launch(void* const* d_in, const int* in_sizes, int n_in,
                              void* d_out, int out_size) {
    const float* z  = (const float*)d_in[0];
    const float* cb = (const float*)d_in[1];
    float* out = (float*)d_out;

    cudaFuncSetAttribute(gemm_argmin_kernel,
                         cudaFuncAttributeMaxDynamicSharedMemorySize, SM_TOTAL);
    const int osmem = 256 * OPAD * (int)sizeof(float);   // 135168
    cudaFuncSetAttribute(output_kernel,
                         cudaFuncAttributeMaxDynamicSharedMemorySize, osmem);

    prep_cb_kernel<<<4, 256>>>(cb);
    gemm_argmin_kernel<<<Nn / MT, 256, SM_TOTAL>>>(z, cb);
    output_kernel<<<Nn / 128, 512, osmem>>>(z, cb, out);
    tail_kernel<<<128, 256>>>(out, out_size);
}

// round 13
// speedup vs baseline: 21.9904x; 1.0217x over previous
#include <cuda_runtime.h>
#include <math_constants.h>
#include <cstdint>

// Shapes (fixed)
#define Bz 32
#define Cc 256
#define HW 1024
#define Nn 32768
#define Kk 1024
#define Dd 256
#define TOTAL_Z 8388608

#define MARGIN 4e-3f
#define CAP 64
#define MT 128          // rows per CTA

// gemm kernel smem map (bytes)
#define SM_CNT   0          // 128 ints
#define SM_ROWM  512        // 128 uints
#define SM_CAND  1024       // 128*64*4 = 32768
#define SM_A     33792      // 65536 (full-D A, bf16 fragment order)
#define SM_B     99328      // 2 x 16384 (B chunk, bf16 fragment order)
#define SM_ZROW  SM_A       // reuse after GEMM: 128*260*4 = 133120
#define SM_TOTAL 166912
#define ZRPAD 260
#define OPAD 132            // output kernel cbT padding

__device__ float          g_B[Kk];        // ||c_k||^2 (sequential fp32 chain)
__device__ unsigned short g_ct[Kk * Dd];  // bf16 codebook, mma-fragment order
__device__ int            g_idx[Nn];
__device__ double         g_loss;

__device__ __forceinline__ uint32_t smem_u32(const void* p) {
    uint32_t a;
    asm("{ .reg .u64 t; cvta.to.shared.u64 t, %1; cvt.u32.u64 %0, t; }"
        : "=r"(a) : "l"(p));
    return a;
}
__device__ __forceinline__ unsigned short bf16r(float v) {
    unsigned short h;
    asm("cvt.rn.bf16.f32 %0, %1;" : "=h"(h) : "f"(v));
    return h;
}
// order-preserving float<->uint map (for unsigned atomicMin)
__device__ __forceinline__ unsigned fenc(float f) {
    unsigned u = __float_as_uint(f);
    return (u & 0x80000000u) ? ~u : (u | 0x80000000u);
}
__device__ __forceinline__ float fdec(unsigned k) {
    unsigned u = (k & 0x80000000u) ? (k & 0x7fffffffu) : ~k;
    return __uint_as_float(u);
}
__device__ __forceinline__ void mma_bf16(float c[4], uint4 a, uint2 b) {
    asm volatile(
        "mma.sync.aligned.m16n8k16.row.col.f32.bf16.bf16.f32 "
        "{%0,%1,%2,%3},{%4,%5,%6,%7},{%8,%9},{%0,%1,%2,%3};"
        : "+f"(c[0]), "+f"(c[1]), "+f"(c[2]), "+f"(c[3])
        : "r"(a.x), "r"(a.y), "r"(a.z), "r"(a.w), "r"(b.x), "r"(b.y));
}

// ---- prep: codebook norms + bf16 fragment-order transpose ----
// For code n, dim d:  t=n>>7, wn=(n>>5)&3, j=(n>>3)&3, tq=n&7
//   c4=d>>6, s=(d>>4)&3, kk=d&15, r=kk>>3, tr=(kk&7)>>1, half=kk&1
//   word = (t*4+c4)*4096 + ((s*16+wn*4+j)*32 + tq*4+tr)*2 + r ; ushort 2w+half
__global__ void prep_cb_kernel(const float* __restrict__ cb) {
    int n = blockIdx.x * blockDim.x + threadIdx.x;
    if (n == 0) g_loss = 0.0;
    if (n < Kk) {
        int t = n >> 7, wn = (n >> 5) & 3, j = (n >> 3) & 3, tq = n & 7;
        float s_ = 0.f;
        #pragma unroll 8
        for (int d = 0; d < Dd; d++) {
            float v = cb[n * Dd + d];
            s_ = __fadd_rn(s_, __fmul_rn(v, v));
            int c4 = d >> 6, ss = (d >> 4) & 3, kk = d & 15;
            int r = kk >> 3, tr = (kk & 7) >> 1, half = kk & 1;
            size_t w = (size_t)(t * 4 + c4) * 4096 +
                       ((ss * 16 + wn * 4 + j) * 32 + tq * 4 + tr) * 2 + r;
            g_ct[w * 2 + half] = bf16r(v);
        }
        g_B[n] = s_;
    }
}

// ---- B chunk staging: contiguous cp.async (16 KB per chunk) ----
__device__ __forceinline__ void issueB(char* smem, int tid, int p, int buf) {
    const char* src = (const char*)g_ct + (size_t)p * 16384 + tid * 16;
    uint32_t dst = smem_u32(smem + SM_B + buf * 16384) + tid * 16;
    #pragma unroll
    for (int it = 0; it < 4; it++)
        asm volatile("cp.async.cg.shared.global [%0], [%1], 16;"
                     :: "r"(dst + it * 4096), "l"(src + it * 4096));
    asm volatile("cp.async.commit_group;");
}

// ============ fused bf16 mma.sync GEMM + row-global streaming argmin ======
// 256 thr = 8 warps (2m x 4n), warp tile 64m x 32n, mma m16n8k16 bf16.
__global__ void __launch_bounds__(256, 1)
gemm_argmin_kernel(const float* __restrict__ z, const float* __restrict__ cb) {
    extern __shared__ char smem[];
    int*      cnt  = (int*)smem;
    unsigned* rowm = (unsigned*)(smem + SM_ROWM);
    int*      cand = (int*)(smem + SM_CAND);
    unsigned short* Asu = (unsigned short*)(smem + SM_A);
    unsigned* Bsu = (unsigned*)(smem + SM_B);

    int tid = threadIdx.x, wid = tid >> 5, lane = tid & 31;
    int wm = wid & 1, wn = wid >> 1, tq = lane >> 2, tr = lane & 3;
    int n0 = blockIdx.x * MT, b = n0 >> 10, hw0 = n0 & 1023;

    if (tid < MT) { cnt[tid] = 0; rowm[tid] = 0xFF800000u; }  // enc(+inf)

    // Stage A: z tile (bf16), pre-permuted to k16 fragment order.
    #pragma unroll 4
    for (int it = 0; it < 32; it++) {
        int d = wid + it * 8;
        float4 v = *(const float4*)(z + (size_t)b * Cc * HW +
                                    (size_t)d * HW + hw0 + lane * 4);
        int sg = d >> 4, kk = d & 15;
        int ktr = (kk & 7) >> 1, khalf = kk & 1, khi = kk >> 3;
        float vv[4] = {v.x, v.y, v.z, v.w};
        #pragma unroll
        for (int q4 = 0; q4 < 4; q4++) {
            int r = lane * 4 + q4;
            int awm = r >> 6, ai = (r >> 4) & 3, ah = (r >> 3) & 1, atq = r & 7;
            int reg = ah + 2 * khi;
            size_t word = ((size_t)(sg * 8 + awm * 4 + ai) * 32 + atq * 4 + ktr) * 4 + reg;
            Asu[word * 2 + khalf] = bf16r(vv[q4]);
        }
    }

    issueB(smem, tid, 0, 0);
    __syncthreads();

    float accf[4][4][4];

    #pragma unroll 1
    for (int p = 0; p < 32; p++) {       // p = t*4 + c4
        int buf = p & 1, c4 = p & 3, t = p >> 2;
        if (p < 31) {
            issueB(smem, tid, p + 1, buf ^ 1);
            asm volatile("cp.async.wait_group 1;" ::: "memory");
        } else {
            asm volatile("cp.async.wait_group 0;" ::: "memory");
        }
        __syncthreads();

        if (c4 == 0) {
            #pragma unroll
            for (int i = 0; i < 4; i++)
                #pragma unroll
                for (int j = 0; j < 4; j++)
                    #pragma unroll
                    for (int q = 0; q < 4; q++) accf[i][j][q] = 0.f;
        }

        const unsigned* Bb = Bsu + buf * 4096;
        const uint4* A4 = (const uint4*)Asu;
        #pragma unroll
        for (int s = 0; s < 4; s++) {    // k16 steps within 64-d chunk
            int sg = c4 * 4 + s;
            uint4 a[4];
            #pragma unroll
            for (int i = 0; i < 4; i++)
                a[i] = A4[(sg * 8 + wm * 4 + i) * 32 + lane];
            uint2 bb[4];
            #pragma unroll
            for (int j = 0; j < 4; j++)
                bb[j] = *(const uint2*)(Bb + ((s * 16 + wn * 4 + j) * 32 + lane) * 2);
            #pragma unroll
            for (int i = 0; i < 4; i++)
                #pragma unroll
                for (int j = 0; j < 4; j++)
                    mma_bf16(accf[i][j], a[i], bb[j]);
        }

        if (c4 == 3) {
            // phase 1: d' = fmaf(-2, dot, B_k); publish row min (encoded)
            float lm[4][2];
            #pragma unroll
            for (int i = 0; i < 4; i++)
                #pragma unroll
                for (int h = 0; h < 2; h++) lm[i][h] = CUDART_INF_F;
            #pragma unroll
            for (int j = 0; j < 4; j++) {
                int k0 = t * 128 + wn * 32 + j * 8 + 2 * tr;
                float2 Bv = *(const float2*)&g_B[k0];
                #pragma unroll
                for (int i = 0; i < 4; i++)
                    #pragma unroll
                    for (int h = 0; h < 2; h++) {
                        float d0 = fmaf(-2.f, accf[i][j][h * 2 + 0], Bv.x);
                        float d1 = fmaf(-2.f, accf[i][j][h * 2 + 1], Bv.y);
                        accf[i][j][h * 2 + 0] = d0;
                        accf[i][j][h * 2 + 1] = d1;
                        lm[i][h] = fminf(lm[i][h], fminf(d0, d1));
                    }
            }
            #pragma unroll
            for (int i = 0; i < 4; i++)
                #pragma unroll
                for (int h = 0; h < 2; h++)
                    atomicMin(&rowm[wm * 64 + i * 16 + h * 8 + tq], fenc(lm[i][h]));
            __syncthreads();
            // phase 2: test against settled row-global running min
            #pragma unroll
            for (int i = 0; i < 4; i++)
                #pragma unroll
                for (int h = 0; h < 2; h++) {
                    int row = wm * 64 + i * 16 + h * 8 + tq;
                    float th = fdec(rowm[row]) + MARGIN;
                    #pragma unroll
                    for (int j = 0; j < 4; j++) {
                        int k0 = t * 128 + wn * 32 + j * 8 + 2 * tr;
                        if (accf[i][j][h * 2 + 0] <= th) {
                            int pos = atomicAdd(&cnt[row], 1);
                            if (pos < CAP) cand[row * CAP + pos] = k0;
                        }
                        if (accf[i][j][h * 2 + 1] <= th) {
                            int pos = atomicAdd(&cnt[row], 1);
                            if (pos < CAP) cand[row * CAP + pos] = k0 + 1;
                        }
                    }
                }
        }
        __syncthreads();
    }

    // -------- exact fp32 rescore (reuse smem for exact z rows) --------
    float* zrow = (float*)(smem + SM_ZROW);     // [128][260], rows 16B-aligned
    #pragma unroll 4
    for (int it = 0; it < 32; it++) {
        int d = wid + it * 8;
        float4 v = *(const float4*)(z + (size_t)b * Cc * HW +
                                    (size_t)d * HW + hw0 + lane * 4);
        int r = lane * 4;
        zrow[(r    ) * ZRPAD + d] = v.x;
        zrow[(r + 1) * ZRPAD + d] = v.y;
        zrow[(r + 2) * ZRPAD + d] = v.z;
        zrow[(r + 3) * ZRPAD + d] = v.w;
    }
    __syncthreads();

    int rr = tid >> 1, part = tid & 1;
    int cr = cnt[rr];
    const float4* zp4 = (const float4*)(zrow + rr * ZRPAD);
    // Zn: sequential chain identical to reference (ascending d)
    float Zn = 0.f;
    #pragma unroll 8
    for (int d4 = 0; d4 < 64; d4++) {
        float4 v = zp4[d4];
        Zn = __fadd_rn(Zn, __fmul_rn(v.x, v.x));
        Zn = __fadd_rn(Zn, __fmul_rn(v.y, v.y));
        Zn = __fadd_rn(Zn, __fmul_rn(v.z, v.z));
        Zn = __fadd_rn(Zn, __fmul_rn(v.w, v.w));
    }

    float bv = CUDART_INF_F; int bk = 0x7fffffff;
    int lim = cr <= CAP ? cr : Kk;      // overflow: exact scan of all codes
    bool ovf = cr > CAP;
    for (int ci = part; ci < lim; ci += 2) {
        int k = ovf ? ci : cand[rr * CAP + ci];
        const float4* c4p = (const float4*)(cb + (size_t)k * Dd);
        float acc = 0.f;
        #pragma unroll 8
        for (int d4 = 0; d4 < 64; d4++) {
            float4 a = zp4[d4];
            float4 c = c4p[d4];
            acc = fmaf(a.x, c.x, acc);
            acc = fmaf(a.y, c.y, acc);
            acc = fmaf(a.z, c.z, acc);
            acc = fmaf(a.w, c.w, acc);
        }
        float dv = fmaf(-2.0f, acc, __fadd_rn(Zn, g_B[k]));
        if (dv < bv || (dv == bv && k < bk)) { bv = dv; bk = k; }
    }
    float ov = __shfl_xor_sync(~0u, bv, 1);
    int   ok = __shfl_xor_sync(~0u, bk, 1);
    if (ov < bv || (ov == bv && ok < bk)) { bv = ov; bk = ok; }
    if (part == 0) g_idx[n0 + rr] = bk;
}

// ---- output: 128-row CTA, transposed smem codebook tile, all-float4 ----
__global__ void __launch_bounds__(512)
output_kernel(const float* __restrict__ z, const float* __restrict__ cb,
              float* __restrict__ out) {
    extern __shared__ float cbT[];           // [256][OPAD]
    __shared__ double wsum[16];

    int tid = threadIdx.x;
    int n0 = blockIdx.x * 128, b = n0 >> 10, hw0 = n0 & 1023;

    {
        int r = tid & 127, cg = tid >> 7;
        int idx = g_idx[n0 + r];
        const float4* src = (const float4*)(cb + (size_t)idx * Dd) + cg * 16;
        #pragma unroll
        for (int m = 0; m < 16; m++) {
            float4 v = src[m];
            int c = cg * 64 + m * 4;
            cbT[(c    ) * OPAD + r] = v.x;
            cbT[(c + 1) * OPAD + r] = v.y;
            cbT[(c + 2) * OPAD + r] = v.z;
            cbT[(c + 3) * OPAD + r] = v.w;
        }
    }
    __syncthreads();

    int lane = tid & 31, w = tid >> 5;
    const float* zb = z   + (size_t)b * Cc * HW + hw0 + lane * 4;
    float*       ob = out + (size_t)b * Cc * HW + hw0 + lane * 4;

    double accd = 0.0;
    #pragma unroll 4
    for (int c = w; c < Cc; c += 16) {
        float4 zv = *(const float4*)(zb + (size_t)c * HW);
        float4 cq = *(const float4*)(cbT + c * OPAD + lane * 4);
        float4 o;
        float dx = __fsub_rn(cq.x, zv.x); o.x = __fadd_rn(zv.x, dx);
        float dy = __fsub_rn(cq.y, zv.y); o.y = __fadd_rn(zv.y, dy);
        float dz = __fsub_rn(cq.z, zv.z); o.z = __fadd_rn(zv.z, dz);
        float dw = __fsub_rn(cq.w, zv.w); o.w = __fadd_rn(zv.w, dw);
        *(float4*)(ob + (size_t)c * HW) = o;
        accd += (double)dx * dx + (double)dy * dy +
                (double)dz * dz + (double)dw * dw;
    }
    #pragma unroll
    for (int o = 16; o; o >>= 1) accd += __shfl_down_sync(0xffffffffu, accd, o);
    if (lane == 0) wsum[w] = accd;
    __syncthreads();
    if (tid == 0) {
        double t = 0.0;
        #pragma unroll
        for (int k = 0; k < 16; k++) t += wsum[k];
        atomicAdd(&g_loss, t);
    }
}

// ---- tail: vq_loss scalar + indices as float ----
__global__ void tail_kernel(float* __restrict__ out, int out_size) {
    int n = blockIdx.x * blockDim.x + threadIdx.x;
    if (n < Nn && out_size >= TOTAL_Z + 1 + Nn)
        out[TOTAL_Z + 1 + n] = (float)g_idx[n];
    if (n == 0 && out_size > TOTAL_Z) {
        double mean = g_loss * (1.0 / (double)TOTAL_Z);
        float cl = (float)mean;
        out[TOTAL_Z] = __fadd_rn(cl, __fmul_rn(0.25f, cl));
    }
}

extern "C" void kernel_launch(void* const* d_in, const int* in_sizes, int n_in,
                              void* d_out, int out_size) {
    const float* z  = (const float*)d_in[0];
    const float* cb = (const float*)d_in[1];
    float* out = (float*)d_out;

    cudaFuncSetAttribute(gemm_argmin_kernel,
                         cudaFuncAttributeMaxDynamicSharedMemorySize, SM_TOTAL);
    const int osmem = 256 * OPAD * (int)sizeof(float);   // 135168
    cudaFuncSetAttribute(output_kernel,
                         cudaFuncAttributeMaxDynamicSharedMemorySize, osmem);

    prep_cb_kernel<<<4, 256>>>(cb);
    gemm_argmin_kernel<<<Nn / MT, 256, SM_TOTAL>>>(z, cb);
    output_kernel<<<Nn / 128, 512, osmem>>>(z, cb, out);
    tail_kernel<<<128, 256>>>(out, out_size);
}

// round 14
// speedup vs baseline: 27.1124x; 1.2329x over previous
#include <cuda_runtime.h>
#include <math_constants.h>
#include <cstdint>

// Shapes (fixed)
#define Bz 32
#define Cc 256
#define HW 1024
#define Nn 32768
#define Kk 1024
#define Dd 256
#define TOTAL_Z 8388608

#define MARGIN 4e-3f
#define CAP 64
#define MT 128          // rows per CTA

// gemm kernel smem map (bytes)
#define SM_CNT   0          // 128 ints (also reused as 8 doubles for wsum)
#define SM_ROWM  512        // 128 uints (encoded row min; reused as sidx)
#define SM_CAND  1024       // 128*64*4 = 32768
#define SM_A     33792      // 65536 (full-D A, bf16 fragment order)
#define SM_B     99328      // 2 x 16384 (B chunk, bf16 fragment order)
#define SM_ZROW  SM_A       // reuse after GEMM: 128*260*4 = 133120
#define SM_CBR   SM_A       // reuse after rescore: [32][257] floats = 32896
#define SM_TOTAL 166912
#define ZRPAD 260

__device__ float          g_B[Kk];        // ||c_k||^2 (sequential fp32 chain)
__device__ unsigned short g_ct[Kk * Dd];  // bf16 codebook, mma-fragment order
__device__ int            g_idx[Nn];
__device__ double         g_loss;

__device__ __forceinline__ uint32_t smem_u32(const void* p) {
    uint32_t a;
    asm("{ .reg .u64 t; cvta.to.shared.u64 t, %1; cvt.u32.u64 %0, t; }"
        : "=r"(a) : "l"(p));
    return a;
}
__device__ __forceinline__ unsigned short bf16r(float v) {
    unsigned short h;
    asm("cvt.rn.bf16.f32 %0, %1;" : "=h"(h) : "f"(v));
    return h;
}
// order-preserving float<->uint map (for unsigned atomicMin)
__device__ __forceinline__ unsigned fenc(float f) {
    unsigned u = __float_as_uint(f);
    return (u & 0x80000000u) ? ~u : (u | 0x80000000u);
}
__device__ __forceinline__ float fdec(unsigned k) {
    unsigned u = (k & 0x80000000u) ? (k & 0x7fffffffu) : ~k;
    return __uint_as_float(u);
}
__device__ __forceinline__ void mma_bf16(float c[4], uint4 a, uint2 b) {
    asm volatile(
        "mma.sync.aligned.m16n8k16.row.col.f32.bf16.bf16.f32 "
        "{%0,%1,%2,%3},{%4,%5,%6,%7},{%8,%9},{%0,%1,%2,%3};"
        : "+f"(c[0]), "+f"(c[1]), "+f"(c[2]), "+f"(c[3])
        : "r"(a.x), "r"(a.y), "r"(a.z), "r"(a.w), "r"(b.x), "r"(b.y));
}

// ---- prep: blocks 0..3 = norms (sequential chain); 4..35 = bf16 transpose --
__global__ void prep_cb_kernel(const float* __restrict__ cb) {
    int bid = blockIdx.x, tid = threadIdx.x;
    if (bid < 4) {
        int n = bid * 256 + tid;
        if (n == 0) g_loss = 0.0;
        const float4* src = (const float4*)(cb + (size_t)n * Dd);
        float s_ = 0.f;
        #pragma unroll 8
        for (int d4 = 0; d4 < 64; d4++) {
            float4 v = src[d4];
            s_ = __fadd_rn(s_, __fmul_rn(v.x, v.x));
            s_ = __fadd_rn(s_, __fmul_rn(v.y, v.y));
            s_ = __fadd_rn(s_, __fmul_rn(v.z, v.z));
            s_ = __fadd_rn(s_, __fmul_rn(v.w, v.w));
        }
        g_B[n] = s_;
    } else {
        int gtid = (bid - 4) * 256 + tid;
        int n = gtid >> 3, part = gtid & 7;
        int t = n >> 7, wn = (n >> 5) & 3, j = (n >> 3) & 3, tq = n & 7;
        const float* src = cb + (size_t)n * Dd + part * 32;
        #pragma unroll 8
        for (int dd = 0; dd < 32; dd++) {
            int d = part * 32 + dd;
            float v = src[dd];
            int c4 = d >> 6, ss = (d >> 4) & 3, kk = d & 15;
            int r = kk >> 3, tr = (kk & 7) >> 1, half = kk & 1;
            size_t w = (size_t)(t * 4 + c4) * 4096 +
                       ((ss * 16 + wn * 4 + j) * 32 + tq * 4 + tr) * 2 + r;
            g_ct[w * 2 + half] = bf16r(v);
        }
    }
}

// ---- B chunk staging: contiguous cp.async (16 KB per chunk) ----
__device__ __forceinline__ void issueB(char* smem, int tid, int p, int buf) {
    const char* src = (const char*)g_ct + (size_t)p * 16384 + tid * 16;
    uint32_t dst = smem_u32(smem + SM_B + buf * 16384) + tid * 16;
    #pragma unroll
    for (int it = 0; it < 4; it++)
        asm volatile("cp.async.cg.shared.global [%0], [%1], 16;"
                     :: "r"(dst + it * 4096), "l"(src + it * 4096));
    asm volatile("cp.async.commit_group;");
}

// ===== fused bf16 GEMM + row-global argmin + exact rescore + output =====
__global__ void __launch_bounds__(256, 1)
gemm_argmin_kernel(const float* __restrict__ z, const float* __restrict__ cb,
                   float* __restrict__ out, int out_size) {
    extern __shared__ char smem[];
    int*      cnt  = (int*)smem;
    unsigned* rowm = (unsigned*)(smem + SM_ROWM);
    int*      cand = (int*)(smem + SM_CAND);
    unsigned short* Asu = (unsigned short*)(smem + SM_A);
    unsigned* Bsu = (unsigned*)(smem + SM_B);

    int tid = threadIdx.x, wid = tid >> 5, lane = tid & 31;
    int wm = wid & 1, wn = wid >> 1, tq = lane >> 2, tr = lane & 3;
    int n0 = blockIdx.x * MT, b = n0 >> 10, hw0 = n0 & 1023;

    if (tid < MT) { cnt[tid] = 0; rowm[tid] = 0xFF800000u; }  // enc(+inf)

    // Stage A: z tile (bf16), pre-permuted to k16 fragment order.
    #pragma unroll 4
    for (int it = 0; it < 32; it++) {
        int d = wid + it * 8;
        float4 v = *(const float4*)(z + (size_t)b * Cc * HW +
                                    (size_t)d * HW + hw0 + lane * 4);
        int sg = d >> 4, kk = d & 15;
        int ktr = (kk & 7) >> 1, khalf = kk & 1, khi = kk >> 3;
        float vv[4] = {v.x, v.y, v.z, v.w};
        #pragma unroll
        for (int q4 = 0; q4 < 4; q4++) {
            int r = lane * 4 + q4;
            int awm = r >> 6, ai = (r >> 4) & 3, ah = (r >> 3) & 1, atq = r & 7;
            int reg = ah + 2 * khi;
            size_t word = ((size_t)(sg * 8 + awm * 4 + ai) * 32 + atq * 4 + ktr) * 4 + reg;
            Asu[word * 2 + khalf] = bf16r(vv[q4]);
        }
    }

    issueB(smem, tid, 0, 0);
    __syncthreads();

    float accf[4][4][4];

    #pragma unroll 1
    for (int p = 0; p < 32; p++) {       // p = t*4 + c4
        int buf = p & 1, c4 = p & 3, t = p >> 2;
        if (p < 31) {
            issueB(smem, tid, p + 1, buf ^ 1);
            asm volatile("cp.async.wait_group 1;" ::: "memory");
        } else {
            asm volatile("cp.async.wait_group 0;" ::: "memory");
        }
        __syncthreads();

        if (c4 == 0) {
            #pragma unroll
            for (int i = 0; i < 4; i++)
                #pragma unroll
                for (int j = 0; j < 4; j++)
                    #pragma unroll
                    for (int q = 0; q < 4; q++) accf[i][j][q] = 0.f;
        }

        const unsigned* Bb = Bsu + buf * 4096;
        const uint4* A4 = (const uint4*)Asu;
        #pragma unroll
        for (int s = 0; s < 4; s++) {    // k16 steps within 64-d chunk
            int sg = c4 * 4 + s;
            uint4 a[4];
            #pragma unroll
            for (int i = 0; i < 4; i++)
                a[i] = A4[(sg * 8 + wm * 4 + i) * 32 + lane];
            uint2 bb[4];
            #pragma unroll
            for (int j = 0; j < 4; j++)
                bb[j] = *(const uint2*)(Bb + ((s * 16 + wn * 4 + j) * 32 + lane) * 2);
            #pragma unroll
            for (int i = 0; i < 4; i++)
                #pragma unroll
                for (int j = 0; j < 4; j++)
                    mma_bf16(accf[i][j], a[i], bb[j]);
        }

        if (c4 == 3) {
            // phase 1: d' = fmaf(-2, dot, B_k); publish row min (encoded)
            float lm[4][2];
            #pragma unroll
            for (int i = 0; i < 4; i++)
                #pragma unroll
                for (int h = 0; h < 2; h++) lm[i][h] = CUDART_INF_F;
            #pragma unroll
            for (int j = 0; j < 4; j++) {
                int k0 = t * 128 + wn * 32 + j * 8 + 2 * tr;
                float2 Bv = *(const float2*)&g_B[k0];
                #pragma unroll
                for (int i = 0; i < 4; i++)
                    #pragma unroll
                    for (int h = 0; h < 2; h++) {
                        float d0 = fmaf(-2.f, accf[i][j][h * 2 + 0], Bv.x);
                        float d1 = fmaf(-2.f, accf[i][j][h * 2 + 1], Bv.y);
                        accf[i][j][h * 2 + 0] = d0;
                        accf[i][j][h * 2 + 1] = d1;
                        lm[i][h] = fminf(lm[i][h], fminf(d0, d1));
                    }
            }
            #pragma unroll
            for (int i = 0; i < 4; i++)
                #pragma unroll
                for (int h = 0; h < 2; h++)
                    atomicMin(&rowm[wm * 64 + i * 16 + h * 8 + tq], fenc(lm[i][h]));
            __syncthreads();
            // phase 2: test against settled row-global running min
            #pragma unroll
            for (int i = 0; i < 4; i++)
                #pragma unroll
                for (int h = 0; h < 2; h++) {
                    int row = wm * 64 + i * 16 + h * 8 + tq;
                    float th = fdec(rowm[row]) + MARGIN;
                    #pragma unroll
                    for (int j = 0; j < 4; j++) {
                        int k0 = t * 128 + wn * 32 + j * 8 + 2 * tr;
                        if (accf[i][j][h * 2 + 0] <= th) {
                            int pos = atomicAdd(&cnt[row], 1);
                            if (pos < CAP) cand[row * CAP + pos] = k0;
                        }
                        if (accf[i][j][h * 2 + 1] <= th) {
                            int pos = atomicAdd(&cnt[row], 1);
                            if (pos < CAP) cand[row * CAP + pos] = k0 + 1;
                        }
                    }
                }
        }
        __syncthreads();
    }

    // -------- exact fp32 rescore (reuse smem for exact z rows) --------
    float* zrow = (float*)(smem + SM_ZROW);     // [128][260], rows 16B-aligned
    #pragma unroll 4
    for (int it = 0; it < 32; it++) {
        int d = wid + it * 8;
        float4 v = *(const float4*)(z + (size_t)b * Cc * HW +
                                    (size_t)d * HW + hw0 + lane * 4);
        int r = lane * 4;
        zrow[(r    ) * ZRPAD + d] = v.x;
        zrow[(r + 1) * ZRPAD + d] = v.y;
        zrow[(r + 2) * ZRPAD + d] = v.z;
        zrow[(r + 3) * ZRPAD + d] = v.w;
    }
    __syncthreads();

    int rr = tid >> 1, part = tid & 1;
    int cr = cnt[rr];
    const float4* zp4 = (const float4*)(zrow + rr * ZRPAD);
    // Zn: sequential chain identical to reference (ascending d)
    float Zn = 0.f;
    #pragma unroll 8
    for (int d4 = 0; d4 < 64; d4++) {
        float4 v = zp4[d4];
        Zn = __fadd_rn(Zn, __fmul_rn(v.x, v.x));
        Zn = __fadd_rn(Zn, __fmul_rn(v.y, v.y));
        Zn = __fadd_rn(Zn, __fmul_rn(v.z, v.z));
        Zn = __fadd_rn(Zn, __fmul_rn(v.w, v.w));
    }

    float bv = CUDART_INF_F; int bk = 0x7fffffff;
    int lim = cr <= CAP ? cr : Kk;      // overflow: exact scan of all codes
    bool ovf = cr > CAP;
    for (int ci = part; ci < lim; ci += 2) {
        int k = ovf ? ci : cand[rr * CAP + ci];
        const float4* c4p = (const float4*)(cb + (size_t)k * Dd);
        float acc = 0.f;
        #pragma unroll 8
        for (int d4 = 0; d4 < 64; d4++) {
            float4 a = zp4[d4];
            float4 c = c4p[d4];
            acc = fmaf(a.x, c.x, acc);
            acc = fmaf(a.y, c.y, acc);
            acc = fmaf(a.z, c.z, acc);
            acc = fmaf(a.w, c.w, acc);
        }
        float dv = fmaf(-2.0f, acc, __fadd_rn(Zn, g_B[k]));
        if (dv < bv || (dv == bv && k < bk)) { bv = dv; bk = k; }
    }
    float ov = __shfl_xor_sync(~0u, bv, 1);
    int   ok = __shfl_xor_sync(~0u, bk, 1);
    if (ov < bv || (ov == bv && ok < bk)) { bv = ov; bk = ok; }
    int* sidx = (int*)rowm;                  // rowm dead; reuse as idx store
    if (part == 0) {
        g_idx[n0 + rr] = bk;
        sidx[rr] = bk;
        if (out_size >= TOTAL_Z + 1 + Nn)
            out[TOTAL_Z + 1 + n0 + rr] = (float)bk;
    }
    __syncthreads();

    // -------- fused output: z_q_st + loss, per 32-row group --------
    float* cbrow = (float*)(smem + SM_CBR);  // [32][257] (zrow dead now)
    double accd = 0.0;
    #pragma unroll 1
    for (int g = 0; g < 4; g++) {
        // gather this group's 32 winning codebook rows (coalesced float4)
        {
            int r = tid >> 3, q8 = tid & 7;
            int idx = sidx[g * 32 + r];
            const float4* src = (const float4*)(cb + (size_t)idx * Dd);
            #pragma unroll
            for (int it = 0; it < 8; it++) {
                float4 vv = src[q8 + it * 8];
                int c = (q8 + it * 8) * 4;
                cbrow[r * 257 + c    ] = vv.x;
                cbrow[r * 257 + c + 1] = vv.y;
                cbrow[r * 257 + c + 2] = vv.z;
                cbrow[r * 257 + c + 3] = vv.w;
            }
        }
        __syncthreads();
        // STE write + loss (byte-identical arithmetic to prior output kernel)
        const float* zp = z   + (size_t)b * Cc * HW + hw0 + g * 32 + lane;
        float*       op = out + (size_t)b * Cc * HW + hw0 + g * 32 + lane;
        #pragma unroll 8
        for (int c = wid; c < Cc; c += 8) {
            float zv = zp[(size_t)c * HW];
            float zq = cbrow[lane * 257 + c];
            float diff = __fsub_rn(zq, zv);
            op[(size_t)c * HW] = __fadd_rn(zv, diff);
            accd += (double)diff * (double)diff;
        }
        __syncthreads();
    }
    #pragma unroll
    for (int o = 16; o; o >>= 1) accd += __shfl_down_sync(0xffffffffu, accd, o);
    double* wsum = (double*)smem;            // cnt region dead
    if (lane == 0) wsum[wid] = accd;
    __syncthreads();
    if (tid == 0) {
        double t = 0.0;
        #pragma unroll
        for (int k = 0; k < 8; k++) t += wsum[k];
        atomicAdd(&g_loss, t);
    }
}

// ---- tail: vq_loss scalar only ----
__global__ void tail_kernel(float* __restrict__ out, int out_size) {
    if (threadIdx.x == 0 && out_size > TOTAL_Z) {
        double mean = g_loss * (1.0 / (double)TOTAL_Z);
        float cl = (float)mean;
        out[TOTAL_Z] = __fadd_rn(cl, __fmul_rn(0.25f, cl));
    }
}

extern "C" void kernel_launch(void* const* d_in, const int* in_sizes, int n_in,
                              void* d_out, int out_size) {
    const float* z  = (const float*)d_in[0];
    const float* cb = (const float*)d_in[1];
    float* out = (float*)d_out;

    cudaFuncSetAttribute(gemm_argmin_kernel,
                         cudaFuncAttributeMaxDynamicSharedMemorySize, SM_TOTAL);

    prep_cb_kernel<<<36, 256>>>(cb);
    gemm_argmin_kernel<<<Nn / MT, 256, SM_TOTAL>>>(z, cb, out, out_size);
    tail_kernel<<<1, 32>>>(out, out_size);
}